// round 1
// baseline (speedup 1.0000x reference)
#include <cuda_runtime.h>

// Problem constants
#define S_LEN   1024
#define D_DIM   64
#define BH_NUM  64            // B*H
#define NROWS   65536         // BH*S
#define NP      513           // used vocab slots p in [0,512] (causal)
#define PSTR    516           // padded row stride for scratch (16B aligned)
#define OUT_ELEMS 4194304     // B*H*S*D

// Scratch (static __device__ — no runtime allocation)
__device__ float g_P[(size_t)NROWS * PSTR];   // P[row,p] = q[row]·Wk[p]
__device__ float g_C[(size_t)NROWS * PSTR];   // shifted weights c[row,m], m=i-j (512 = lumped)
__device__ float g_M[NROWS];                  // row max of logits
__device__ float g_SInv[NROWS];               // 1/sumexp per row

// ---------------------------------------------------------------------------
// Kernel A: P = Q @ Wk^T  (M=65536, N=513, K=64)
// ---------------------------------------------------------------------------
__global__ void __launch_bounds__(256) kernA(const float* __restrict__ q,
                                             const float* __restrict__ Wk) {
    __shared__ float sQ[64][65];
    __shared__ float sW[64][65];
    const int r0 = blockIdx.x * 64;
    const int p0 = blockIdx.y * 64;
    const int tid = threadIdx.x;

    for (int e = tid; e < 1024; e += 256) {
        int r = e >> 4, c4 = (e & 15) << 2;
        float4 vv = *reinterpret_cast<const float4*>(&q[(size_t)(r0 + r) * D_DIM + c4]);
        sQ[r][c4] = vv.x; sQ[r][c4 + 1] = vv.y; sQ[r][c4 + 2] = vv.z; sQ[r][c4 + 3] = vv.w;
    }
    for (int e = tid; e < 1024; e += 256) {
        int r = e >> 4, c4 = (e & 15) << 2;
        int p = p0 + r;
        if (p < NP) {
            float4 vv = *reinterpret_cast<const float4*>(&Wk[(size_t)p * D_DIM + c4]);
            sW[r][c4] = vv.x; sW[r][c4 + 1] = vv.y; sW[r][c4 + 2] = vv.z; sW[r][c4 + 3] = vv.w;
        } else {
            sW[r][c4] = 0.f; sW[r][c4 + 1] = 0.f; sW[r][c4 + 2] = 0.f; sW[r][c4 + 3] = 0.f;
        }
    }
    __syncthreads();

    const int tx = tid & 15, ty = tid >> 4;
    const int rl = ty << 2, cl = tx << 2;
    float acc[4][4] = {};
    #pragma unroll 8
    for (int d = 0; d < 64; ++d) {
        float a[4], b[4];
        #pragma unroll
        for (int t = 0; t < 4; ++t) { a[t] = sQ[rl + t][d]; b[t] = sW[cl + t][d]; }
        #pragma unroll
        for (int ri = 0; ri < 4; ++ri)
            #pragma unroll
            for (int ci = 0; ci < 4; ++ci)
                acc[ri][ci] += a[ri] * b[ci];
    }
    #pragma unroll
    for (int ri = 0; ri < 4; ++ri)
        #pragma unroll
        for (int ci = 0; ci < 4; ++ci) {
            int p = p0 + cl + ci;
            if (p < NP) g_P[(size_t)(r0 + rl + ri) * PSTR + p] = acc[ri][ci];
        }
}

// ---------------------------------------------------------------------------
// Kernel B: per (bh, 64-row i-block): stream causal j-tiles.
// logits = Q@K^T + P-bias (masked -> -1e30), write RAW logits to weights buf,
// maintain online row max / sumexp; store m and 1/s at the end.
// ---------------------------------------------------------------------------
__global__ void __launch_bounds__(256) kernB(const float* __restrict__ q,
                                             const float* __restrict__ kmat,
                                             float* __restrict__ wbuf) {
    __shared__ float sQ[64][65];
    __shared__ float sK[64][65];
    __shared__ float sM[64], sS[64];
    const int bh = blockIdx.y;
    const int ib = 15 - (int)blockIdx.x;       // heavy blocks launch first
    const int i0 = ib * 64;
    const int rowbase = bh * S_LEN + i0;
    const int tid = threadIdx.x;

    for (int e = tid; e < 1024; e += 256) {
        int r = e >> 4, c4 = (e & 15) << 2;
        float4 vv = *reinterpret_cast<const float4*>(&q[(size_t)(rowbase + r) * D_DIM + c4]);
        sQ[r][c4] = vv.x; sQ[r][c4 + 1] = vv.y; sQ[r][c4 + 2] = vv.z; sQ[r][c4 + 3] = vv.w;
    }
    if (tid < 64) { sM[tid] = -1e30f; sS[tid] = 0.f; }

    const int tx = tid & 15, ty = tid >> 4;
    const int rl = ty << 2, cl = tx << 2;

    for (int jb = 0; jb <= ib; ++jb) {
        const int j0 = jb * 64;
        __syncthreads();
        for (int e = tid; e < 1024; e += 256) {
            int r = e >> 4, c4 = (e & 15) << 2;
            float4 vv = *reinterpret_cast<const float4*>(&kmat[(size_t)(bh * S_LEN + j0 + r) * D_DIM + c4]);
            sK[r][c4] = vv.x; sK[r][c4 + 1] = vv.y; sK[r][c4 + 2] = vv.z; sK[r][c4 + 3] = vv.w;
        }
        __syncthreads();

        float acc[4][4] = {};
        #pragma unroll 8
        for (int d = 0; d < 64; ++d) {
            float a[4], b[4];
            #pragma unroll
            for (int t = 0; t < 4; ++t) { a[t] = sQ[rl + t][d]; b[t] = sK[cl + t][d]; }
            #pragma unroll
            for (int ri = 0; ri < 4; ++ri)
                #pragma unroll
                for (int ci = 0; ci < 4; ++ci)
                    acc[ri][ci] += a[ri] * b[ci];
        }

        // relative-key bias + causal mask
        #pragma unroll
        for (int ri = 0; ri < 4; ++ri) {
            const int i = i0 + rl + ri;
            const size_t prow = (size_t)(bh * S_LEN + i) * PSTR;
            #pragma unroll
            for (int ci = 0; ci < 4; ++ci) {
                const int j = j0 + cl + ci;
                int p = j - i + 512; if (p < 0) p = 0;
                acc[ri][ci] += g_P[prow + p];
                if (j > i) acc[ri][ci] = -1e30f;
            }
        }

        // online softmax stats (each row owned by one 16-lane group)
        #pragma unroll
        for (int ri = 0; ri < 4; ++ri) {
            const int r = rl + ri;
            float mx = fmaxf(fmaxf(acc[ri][0], acc[ri][1]), fmaxf(acc[ri][2], acc[ri][3]));
            #pragma unroll
            for (int o = 8; o >= 1; o >>= 1) mx = fmaxf(mx, __shfl_xor_sync(0xffffffffu, mx, o));
            const float oldm = sM[r];
            const float newm = fmaxf(oldm, mx);
            float se = __expf(acc[ri][0] - newm) + __expf(acc[ri][1] - newm)
                     + __expf(acc[ri][2] - newm) + __expf(acc[ri][3] - newm);
            #pragma unroll
            for (int o = 8; o >= 1; o >>= 1) se += __shfl_xor_sync(0xffffffffu, se, o);
            if (tx == 0) { sS[r] = sS[r] * __expf(oldm - newm) + se; sM[r] = newm; }
        }

        // write raw logits into the weights region
        #pragma unroll
        for (int ri = 0; ri < 4; ++ri) {
            float4 vv = make_float4(acc[ri][0], acc[ri][1], acc[ri][2], acc[ri][3]);
            *reinterpret_cast<float4*>(&wbuf[(size_t)(rowbase + rl + ri) * S_LEN + j0 + cl]) = vv;
        }
    }
    __syncthreads();
    if (tid < 64) {
        g_M[rowbase + tid] = sM[tid];
        g_SInv[rowbase + tid] = 1.0f / sS[tid];
    }
}

// ---------------------------------------------------------------------------
// Kernel C: per (bh, 64-row i-block): normalize logits -> weights (in place),
// zero strict-upper tiles, accumulate out1 = W@V, scatter shifted weights
// into g_C (m = i-j; m>=512 lumped into slot 512; m>i zero-filled).
// ---------------------------------------------------------------------------
__global__ void __launch_bounds__(256) kernC(const float* __restrict__ v,
                                             float* __restrict__ wbuf,
                                             float* __restrict__ outp) {
    __shared__ float sV[64][65];
    __shared__ float sW[64][65];
    __shared__ float sMl[64], sIl[64], sCs[64];
    const int bh = blockIdx.y;
    const int ib = 15 - (int)blockIdx.x;
    const int i0 = ib * 64;
    const int rowbase = bh * S_LEN + i0;
    const int tid = threadIdx.x;

    if (tid < 64) {
        sMl[tid] = g_M[rowbase + tid];
        sIl[tid] = g_SInv[rowbase + tid];
        sCs[tid] = 0.f;
    }
    __syncthreads();

    const int tx = tid & 15, ty = tid >> 4;
    const int rl = ty << 2, cl = tx << 2;
    float acc[4][4] = {};

    for (int jb = 0; jb < 16; ++jb) {
        const int j0 = jb * 64;
        if (jb > ib) {  // strict upper triangle: weights are exactly 0
            const float4 z = make_float4(0.f, 0.f, 0.f, 0.f);
            #pragma unroll
            for (int ri = 0; ri < 4; ++ri)
                *reinterpret_cast<float4*>(&wbuf[(size_t)(rowbase + rl + ri) * S_LEN + j0 + cl]) = z;
            continue;
        }
        __syncthreads();
        for (int e = tid; e < 1024; e += 256) {
            int r = e >> 4, c4 = (e & 15) << 2;
            float4 vv = *reinterpret_cast<const float4*>(&v[(size_t)(bh * S_LEN + j0 + r) * D_DIM + c4]);
            sV[r][c4] = vv.x; sV[r][c4 + 1] = vv.y; sV[r][c4 + 2] = vv.z; sV[r][c4 + 3] = vv.w;
        }
        for (int e = tid; e < 1024; e += 256) {
            int r = e >> 4, c4 = (e & 15) << 2;
            size_t a = (size_t)(rowbase + r) * S_LEN + j0 + c4;
            float4 l = *reinterpret_cast<float4*>(&wbuf[a]);
            const float m = sMl[r], inv = sIl[r];
            float4 w;
            w.x = __expf(l.x - m) * inv;
            w.y = __expf(l.y - m) * inv;
            w.z = __expf(l.z - m) * inv;
            w.w = __expf(l.w - m) * inv;
            *reinterpret_cast<float4*>(&wbuf[a]) = w;
            sW[r][c4] = w.x; sW[r][c4 + 1] = w.y; sW[r][c4 + 2] = w.z; sW[r][c4 + 3] = w.w;
        }
        __syncthreads();

        #pragma unroll 8
        for (int j = 0; j < 64; ++j) {
            float a[4], b[4];
            #pragma unroll
            for (int t = 0; t < 4; ++t) { a[t] = sW[rl + t][j]; b[t] = sV[j][cl + t]; }
            #pragma unroll
            for (int ri = 0; ri < 4; ++ri)
                #pragma unroll
                for (int ci = 0; ci < 4; ++ci)
                    acc[ri][ci] += a[ri] * b[ci];
        }

        // scatter shifted weights
        for (int e = tid; e < 4096; e += 256) {
            int r = e >> 6, jj = e & 63;
            int i = i0 + r, j = j0 + jj;
            int mm = i - j;
            float w = sW[r][jj];
            if (mm >= 0) {
                if (mm < 512) g_C[(size_t)(rowbase + r) * PSTR + mm] = w;
                else          atomicAdd(&sCs[r], w);
            }
        }
    }
    __syncthreads();

    #pragma unroll
    for (int ri = 0; ri < 4; ++ri) {
        float4 o = make_float4(acc[ri][0], acc[ri][1], acc[ri][2], acc[ri][3]);
        *reinterpret_cast<float4*>(&outp[(size_t)(rowbase + rl + ri) * D_DIM + cl]) = o;
    }
    if (tid < 64) g_C[(size_t)(rowbase + tid) * PSTR + 512] = sCs[tid];
    if (i0 < 512) {  // rows i<512: slots m in (i, 512) were never written
        for (int idx = tid; idx < 64 * 512; idx += 256) {
            int r = idx >> 9, mm = idx & 511;
            int i = i0 + r;
            if (mm > i) g_C[(size_t)(rowbase + r) * PSTR + mm] = 0.f;
        }
    }
}

// ---------------------------------------------------------------------------
// Kernel D: out += C @ Wv_rev   (M=65536, K=513, N=64), Wv_rev[m] = Wv[512-m]
// ---------------------------------------------------------------------------
__global__ void __launch_bounds__(256) kernD(const float* __restrict__ Wv,
                                             float* __restrict__ outp) {
    __shared__ float sC[64][65];
    __shared__ float sB[64][65];
    const int r0 = blockIdx.x * 64;
    const int tid = threadIdx.x;
    const int tx = tid & 15, ty = tid >> 4;
    const int rl = ty << 2, cl = tx << 2;
    float acc[4][4] = {};

    for (int m0 = 0; m0 < NP; m0 += 64) {
        __syncthreads();
        for (int e = tid; e < 4096; e += 256) {
            int r = e >> 6, mm = e & 63;
            int m = m0 + mm;
            sC[r][mm] = (m < NP) ? g_C[(size_t)(r0 + r) * PSTR + m] : 0.f;
        }
        for (int e = tid; e < 4096; e += 256) {
            int mm = e >> 6, d = e & 63;
            int m = m0 + mm;
            sB[mm][d] = (m < NP) ? Wv[(size_t)(512 - m) * D_DIM + d] : 0.f;
        }
        __syncthreads();
        #pragma unroll 8
        for (int j = 0; j < 64; ++j) {
            float a[4], b[4];
            #pragma unroll
            for (int t = 0; t < 4; ++t) { a[t] = sC[rl + t][j]; b[t] = sB[j][cl + t]; }
            #pragma unroll
            for (int ri = 0; ri < 4; ++ri)
                #pragma unroll
                for (int ci = 0; ci < 4; ++ci)
                    acc[ri][ci] += a[ri] * b[ci];
        }
    }
    #pragma unroll
    for (int ri = 0; ri < 4; ++ri) {
        size_t a = (size_t)(r0 + rl + ri) * D_DIM + cl;
        float4 o = *reinterpret_cast<float4*>(&outp[a]);
        o.x += acc[ri][0]; o.y += acc[ri][1]; o.z += acc[ri][2]; o.w += acc[ri][3];
        *reinterpret_cast<float4*>(&outp[a]) = o;
    }
}

// ---------------------------------------------------------------------------
extern "C" void kernel_launch(void* const* d_in, const int* in_sizes, int n_in,
                              void* d_out, int out_size) {
    const float* q  = (const float*)d_in[0];
    const float* k  = (const float*)d_in[1];
    const float* v  = (const float*)d_in[2];
    const float* Wk = (const float*)d_in[3];
    const float* Wv = (const float*)d_in[4];
    // d_in[5] = rel_positions (recomputed analytically), d_in[6] = mask (causal, recomputed)

    float* outp = (float*)d_out;            // (B,H,S,D) output
    float* wbuf = outp + OUT_ELEMS;         // (B,H,S,S) weights

    kernA<<<dim3(1024, 9), 256>>>(q, Wk);
    kernB<<<dim3(16, 64), 256>>>(q, k, wbuf);
    kernC<<<dim3(16, 64), 256>>>(v, wbuf, outp);
    kernD<<<dim3(1024), 256>>>(Wv, outp);
}

// round 2
// speedup vs baseline: 1.2175x; 1.2175x over previous
#include <cuda_runtime.h>

#define S_LEN 1024
#define NP 513
#define PSTR 516
#define OUT_ELEMS 4194304
#define NROWS 65536

__device__ float g_P[(size_t)NROWS * PSTR];   // P[row,p] = q[row]·Wk[p]
__device__ float g_C[(size_t)NROWS * PSTR];   // shifted weights c[row,m]

// ---------------------------------------------------------------------------
// Kernel A: P = Q @ Wk^T  (vectorized microkernel + causal tile skip)
// ---------------------------------------------------------------------------
__global__ void __launch_bounds__(256) kernA(const float* __restrict__ q,
                                             const float* __restrict__ Wk) {
    const int r0 = blockIdx.x * 64;
    const int p0 = blockIdx.y * 64;
    const int i0 = r0 & (S_LEN - 1);
    if (p0 + 63 < 449 - i0) return;   // tile entirely below min needed p = 512-(i0+63)
    __shared__ float sQT[64][68];
    __shared__ float sWT[64][68];
    const int tid = threadIdx.x;
    for (int e = tid; e < 1024; e += 256) {
        int r = e >> 4, c4 = (e & 15) << 2;
        float4 vv = *(const float4*)(q + (size_t)(r0 + r) * 64 + c4);
        sQT[c4+0][r]=vv.x; sQT[c4+1][r]=vv.y; sQT[c4+2][r]=vv.z; sQT[c4+3][r]=vv.w;
    }
    for (int e = tid; e < 1024; e += 256) {
        int r = e >> 4, c4 = (e & 15) << 2;
        int p = p0 + r;
        float4 vv = make_float4(0.f, 0.f, 0.f, 0.f);
        if (p < NP) vv = *(const float4*)(Wk + (size_t)p * 64 + c4);
        sWT[c4+0][r]=vv.x; sWT[c4+1][r]=vv.y; sWT[c4+2][r]=vv.z; sWT[c4+3][r]=vv.w;
    }
    __syncthreads();
    const int tx = tid & 15, ty = tid >> 4;
    const int rl = ty << 2, cl = tx << 2;
    float acc[4][4] = {};
    #pragma unroll 16
    for (int d = 0; d < 64; ++d) {
        float4 a4 = *(const float4*)&sQT[d][rl];
        float4 b4 = *(const float4*)&sWT[d][cl];
        const float a[4] = {a4.x, a4.y, a4.z, a4.w};
        const float b[4] = {b4.x, b4.y, b4.z, b4.w};
        #pragma unroll
        for (int ri = 0; ri < 4; ++ri)
            #pragma unroll
            for (int ci = 0; ci < 4; ++ci)
                acc[ri][ci] += a[ri] * b[ci];
    }
    #pragma unroll
    for (int ri = 0; ri < 4; ++ri) {
        const size_t row = (size_t)(r0 + rl + ri) * PSTR;
        #pragma unroll
        for (int ci = 0; ci < 4; ++ci) {
            int p = p0 + cl + ci;
            if (p < NP) g_P[row + p] = acc[ri][ci];
        }
    }
}

// ---------------------------------------------------------------------------
// Fused B+C: flash-style single-exp attention.
// Pass1 per j-tile: QK^T + bias + mask, online max/sum, write E=exp(l-m_run)
// to wbuf, accumulate O with rescaling, record per-tile running max.
// Pass2: rescale wbuf tiles by exp(m_tile - m_fin)/s (multiplies only),
// zero upper triangle, scatter shifted weights into g_C.
// ---------------------------------------------------------------------------
__global__ void __launch_bounds__(256) kernBC(const float* __restrict__ q,
                                              const float* __restrict__ kmat,
                                              const float* __restrict__ v,
                                              float* __restrict__ wbuf,
                                              float* __restrict__ outp) {
    extern __shared__ float dsm[];
    float (*sQT)[68] = (float(*)[68])(dsm);
    float (*sKT)[68] = (float(*)[68])(dsm + 4352);
    float (*sV)[68]  = (float(*)[68])(dsm + 8704);
    float (*sET)[68] = (float(*)[68])(dsm + 13056);
    float *sMh  = dsm + 17408;   // [16][64] per-tile running max
    float *sM   = dsm + 18432;
    float *sS   = dsm + 18496;
    float *sCs  = dsm + 18560;
    float *sInv = dsm + 18624;
    float *sFac = dsm + 18688;

    const int bh = blockIdx.y;
    const int ib = 15 - (int)blockIdx.x;     // heavy blocks first
    const int i0 = ib * 64;
    const int rowbase = bh * S_LEN + i0;
    const int tid = threadIdx.x;
    const int tx = tid & 15, ty = tid >> 4;
    const int rl = ty << 2, cl = tx << 2;
    const int lane = tid & 31;

    for (int e = tid; e < 1024; e += 256) {
        int r = e >> 4, c4 = (e & 15) << 2;
        float4 vv = *(const float4*)(q + (size_t)(rowbase + r) * 64 + c4);
        sQT[c4+0][r]=vv.x; sQT[c4+1][r]=vv.y; sQT[c4+2][r]=vv.z; sQT[c4+3][r]=vv.w;
    }
    if (tid < 64) { sM[tid] = -1e30f; sS[tid] = 0.f; sCs[tid] = 0.f; }

    float accO[4][4] = {};

    for (int jb = 0; jb <= ib; ++jb) {
        const int j0 = jb * 64;
        __syncthreads();
        for (int e = tid; e < 1024; e += 256) {
            int r = e >> 4, c4 = (e & 15) << 2;
            float4 vv = *(const float4*)(kmat + (size_t)(bh * S_LEN + j0 + r) * 64 + c4);
            sKT[c4+0][r]=vv.x; sKT[c4+1][r]=vv.y; sKT[c4+2][r]=vv.z; sKT[c4+3][r]=vv.w;
        }
        for (int e = tid; e < 1024; e += 256) {
            int r = e >> 4, c4 = (e & 15) << 2;
            float4 vv = *(const float4*)(v + (size_t)(bh * S_LEN + j0 + r) * 64 + c4);
            *(float4*)&sV[r][c4] = vv;
        }
        __syncthreads();

        float accQ[4][4] = {};
        #pragma unroll 16
        for (int d = 0; d < 64; ++d) {
            float4 a4 = *(const float4*)&sQT[d][rl];
            float4 b4 = *(const float4*)&sKT[d][cl];
            const float a[4] = {a4.x, a4.y, a4.z, a4.w};
            const float b[4] = {b4.x, b4.y, b4.z, b4.w};
            #pragma unroll
            for (int ri = 0; ri < 4; ++ri)
                #pragma unroll
                for (int ci = 0; ci < 4; ++ci)
                    accQ[ri][ci] += a[ri] * b[ci];
        }

        // relative-key bias + causal mask
        #pragma unroll
        for (int ri = 0; ri < 4; ++ri) {
            const int i = i0 + rl + ri;
            const size_t prow = (size_t)(rowbase + rl + ri) * PSTR;
            #pragma unroll
            for (int ci = 0; ci < 4; ++ci) {
                const int j = j0 + cl + ci;
                int p = j - i + 512; if (p < 0) p = 0;
                accQ[ri][ci] += g_P[prow + p];
                if (j > i) accQ[ri][ci] = -1e30f;
            }
        }

        // online stats + E + O-rescale (one exp per element total)
        float ev[4][4];
        #pragma unroll
        for (int ri = 0; ri < 4; ++ri) {
            const int r = rl + ri;
            float mx = fmaxf(fmaxf(accQ[ri][0], accQ[ri][1]), fmaxf(accQ[ri][2], accQ[ri][3]));
            #pragma unroll
            for (int off = 8; off >= 1; off >>= 1)
                mx = fmaxf(mx, __shfl_xor_sync(0xffffffffu, mx, off));
            const float oldm = sM[r];
            const float newm = fmaxf(oldm, mx);
            float cfr0 = (tx == 0) ? __expf(oldm - newm) : 0.f;
            const float cfr = __shfl_sync(0xffffffffu, cfr0, lane & 16);
            #pragma unroll
            for (int ci = 0; ci < 4; ++ci) ev[ri][ci] = __expf(accQ[ri][ci] - newm);
            float se = ev[ri][0] + ev[ri][1] + ev[ri][2] + ev[ri][3];
            #pragma unroll
            for (int off = 8; off >= 1; off >>= 1)
                se += __shfl_xor_sync(0xffffffffu, se, off);
            if (tx == 0) { sS[r] = sS[r] * cfr + se; sM[r] = newm; sMh[jb * 64 + r] = newm; }
            #pragma unroll
            for (int ci = 0; ci < 4; ++ci) accO[ri][ci] *= cfr;
        }

        // write E to wbuf (raw, rescaled in pass2) + transposed smem for E@V
        #pragma unroll
        for (int ri = 0; ri < 4; ++ri) {
            float4 w = make_float4(ev[ri][0], ev[ri][1], ev[ri][2], ev[ri][3]);
            *(float4*)(wbuf + (size_t)(rowbase + rl + ri) * S_LEN + j0 + cl) = w;
            #pragma unroll
            for (int ci = 0; ci < 4; ++ci) sET[cl + ci][rl + ri] = ev[ri][ci];
        }
        __syncthreads();

        // accO += E @ V
        #pragma unroll 16
        for (int j = 0; j < 64; ++j) {
            float4 a4 = *(const float4*)&sET[j][rl];
            float4 b4 = *(const float4*)&sV[j][cl];
            const float a[4] = {a4.x, a4.y, a4.z, a4.w};
            const float b[4] = {b4.x, b4.y, b4.z, b4.w};
            #pragma unroll
            for (int ri = 0; ri < 4; ++ri)
                #pragma unroll
                for (int ci = 0; ci < 4; ++ci)
                    accO[ri][ci] += a[ri] * b[ci];
        }
    }

    __syncthreads();
    if (tid < 64) sInv[tid] = 1.0f / sS[tid];
    __syncthreads();

    // first-term output (rel-val GEMM added by kernD)
    #pragma unroll
    for (int ri = 0; ri < 4; ++ri) {
        const float inv = sInv[rl + ri];
        float4 o = make_float4(accO[ri][0]*inv, accO[ri][1]*inv, accO[ri][2]*inv, accO[ri][3]*inv);
        *(float4*)(outp + (size_t)(rowbase + rl + ri) * 64 + cl) = o;
    }

    // pass2: finalize weights in wbuf + scatter shifted weights into g_C
    for (int jb = 0; jb < 16; ++jb) {
        const int j0 = jb * 64;
        if (jb > ib) {   // strict upper triangle: exact zeros
            const float4 z = make_float4(0.f, 0.f, 0.f, 0.f);
            for (int e = tid; e < 1024; e += 256) {
                int r = e >> 4, c4 = (e & 15) << 2;
                *(float4*)(wbuf + (size_t)(rowbase + r) * S_LEN + j0 + c4) = z;
            }
            continue;
        }
        __syncthreads();
        if (tid < 64) sFac[tid] = __expf(sMh[jb * 64 + tid] - sM[tid]) * sInv[tid];
        __syncthreads();
        for (int e = tid; e < 1024; e += 256) {
            int r = e >> 4, c4 = (e & 15) << 2;
            size_t addr = (size_t)(rowbase + r) * S_LEN + j0 + c4;
            float4 w = *(float4*)(wbuf + addr);
            const float f = sFac[r];
            w.x *= f; w.y *= f; w.z *= f; w.w *= f;
            *(float4*)(wbuf + addr) = w;
            const int i = i0 + r;
            const size_t crow = (size_t)(rowbase + r) * PSTR;
            const float wv[4] = {w.x, w.y, w.z, w.w};
            #pragma unroll
            for (int t = 0; t < 4; ++t) {
                int mm = i - (j0 + c4 + t);
                if (mm >= 0) {
                    if (mm < 512) g_C[crow + mm] = wv[t];
                    else          atomicAdd(&sCs[r], wv[t]);
                }
            }
        }
    }
    __syncthreads();
    if (tid < 64) g_C[(size_t)(rowbase + tid) * PSTR + 512] = sCs[tid];
    if (i0 < 512) {  // zero-fill never-written slots (m in (i,512))
        for (int idx = tid; idx < 64 * 512; idx += 256) {
            int r = idx >> 9, mm = idx & 511;
            if (mm > i0 + r) g_C[(size_t)(rowbase + r) * PSTR + mm] = 0.f;
        }
    }
}

// ---------------------------------------------------------------------------
// Kernel D: out += C @ Wv_rev, K-loop truncated at m <= i0+63 (causal zeros)
// ---------------------------------------------------------------------------
__global__ void __launch_bounds__(256) kernD(const float* __restrict__ Wv,
                                             float* __restrict__ outp) {
    __shared__ float sCT[64][68];   // [m][r]
    __shared__ float sB[64][68];    // [m][d]
    const int r0 = blockIdx.x * 64;
    const int i0 = r0 & (S_LEN - 1);
    const int mEnd = min(NP, i0 + 64);
    const int tid = threadIdx.x;
    const int tx = tid & 15, ty = tid >> 4;
    const int rl = ty << 2, cl = tx << 2;
    float acc[4][4] = {};

    for (int m0 = 0; m0 < mEnd; m0 += 64) {
        __syncthreads();
        for (int e = tid; e < 1024; e += 256) {
            int r = e >> 4, c4 = (e & 15) << 2;
            float4 vv = make_float4(0.f, 0.f, 0.f, 0.f);
            if (m0 + c4 < NP)   // row has PSTR=516 slots; m=513..515 are zero
                vv = *(const float4*)(g_C + (size_t)(r0 + r) * PSTR + m0 + c4);
            sCT[c4+0][r]=vv.x; sCT[c4+1][r]=vv.y; sCT[c4+2][r]=vv.z; sCT[c4+3][r]=vv.w;
        }
        for (int e = tid; e < 1024; e += 256) {
            int mm = e >> 4, c4 = (e & 15) << 2;
            int m = m0 + mm;
            float4 vv = make_float4(0.f, 0.f, 0.f, 0.f);
            if (m < NP) vv = *(const float4*)(Wv + (size_t)(512 - m) * 64 + c4);
            *(float4*)&sB[mm][c4] = vv;
        }
        __syncthreads();
        #pragma unroll 16
        for (int j = 0; j < 64; ++j) {
            float4 a4 = *(const float4*)&sCT[j][rl];
            float4 b4 = *(const float4*)&sB[j][cl];
            const float a[4] = {a4.x, a4.y, a4.z, a4.w};
            const float b[4] = {b4.x, b4.y, b4.z, b4.w};
            #pragma unroll
            for (int ri = 0; ri < 4; ++ri)
                #pragma unroll
                for (int ci = 0; ci < 4; ++ci)
                    acc[ri][ci] += a[ri] * b[ci];
        }
    }
    #pragma unroll
    for (int ri = 0; ri < 4; ++ri) {
        size_t a = (size_t)(r0 + rl + ri) * 64 + cl;
        float4 o = *(float4*)(outp + a);
        o.x += acc[ri][0]; o.y += acc[ri][1]; o.z += acc[ri][2]; o.w += acc[ri][3];
        *(float4*)(outp + a) = o;
    }
}

// ---------------------------------------------------------------------------
extern "C" void kernel_launch(void* const* d_in, const int* in_sizes, int n_in,
                              void* d_out, int out_size) {
    const float* q  = (const float*)d_in[0];
    const float* k  = (const float*)d_in[1];
    const float* v  = (const float*)d_in[2];
    const float* Wk = (const float*)d_in[3];
    const float* Wv = (const float*)d_in[4];
    // d_in[5] = rel_positions (analytic), d_in[6] = mask (causal, analytic)

    float* outp = (float*)d_out;            // (B,H,S,D)
    float* wbuf = outp + OUT_ELEMS;         // (B,H,S,S) weights

    cudaFuncSetAttribute(kernBC, cudaFuncAttributeMaxDynamicSharedMemorySize, 75008);
    kernA<<<dim3(1024, 9), 256>>>(q, Wk);
    kernBC<<<dim3(16, 64), 256, 75008>>>(q, k, v, wbuf, outp);
    kernD<<<dim3(1024), 256>>>(Wv, outp);
}